// round 14
// baseline (speedup 1.0000x reference)
#include <cuda_runtime.h>
#include <cuda_fp16.h>
#include <cstdint>

// ChannelAttentionModule: out = x + (F @ softmax(F^T F)^T), F = x.reshape(B,C,N)
// B=8, C=64, N=4096. fp16 mma.sync FA2, one-hot-aware tile skip.
// R14: O accumulator lives in SMEM (loaded only on the ~2 non-skipped tiles)
// -> ~32 fewer live registers, no spills. Running max seeded from precomputed
// self-logits diag[n] = sum_c fp16(x)^2 -> every non-self tile skips from t=0.

constexpr int C    = 64;
constexpr int NPOS = 4096;
constexpr int NB   = 8;
constexpr int BM   = 128;
constexpr int BN   = 64;
constexpr int NT   = NPOS / BN;    // 64 tiles
constexpr int LDKB = 144;
constexpr int LDQ  = 272;
constexpr int LDO  = 68;

__device__ __half g_cn[(size_t)NB * C * NPOS];   // fp16 x, [b][c][n]
__device__ float  g_diag[NB * NPOS];             // self logits (minus margin)

__global__ void prep_kernel(const float* __restrict__ x) {
    size_t i = ((size_t)blockIdx.x * 256 + threadIdx.x) * 4;
    float4 v = *(const float4*)(x + i);
    *(__half2*)(g_cn + i)     = __floats2half2_rn(v.x, v.y);
    *(__half2*)(g_cn + i + 2) = __floats2half2_rn(v.z, v.w);
}

__global__ void diag_kernel() {
    int b = blockIdx.y;
    int n = blockIdx.x * 256 + threadIdx.x;
    const __half* p = g_cn + (size_t)b * C * NPOS + n;
    float s = 0.f;
    #pragma unroll
    for (int c = 0; c < C; ++c) {
        float v = __half2float(p[(size_t)c * NPOS]);
        s = fmaf(v, v, s);
    }
    g_diag[b * NPOS + n] = s - 0.5f;   // safe lower bound on the row max logit
}

// ---------------- PTX helpers ----------------
__device__ __forceinline__ uint32_t smem_u32(const void* p) {
    uint32_t a;
    asm("{ .reg .u64 t; cvta.to.shared.u64 t, %1; cvt.u32.u64 %0, t; }" : "=r"(a) : "l"(p));
    return a;
}
__device__ __forceinline__ void cpa16(uint32_t dst, const void* src) {
    asm volatile("cp.async.ca.shared.global [%0], [%1], 16;"
                 :: "r"(dst), "l"(__cvta_generic_to_global(src)));
}
#define CP_COMMIT() asm volatile("cp.async.commit_group;" ::: "memory")
#define CP_WAIT1()  asm volatile("cp.async.wait_group 1;" ::: "memory")

__device__ __forceinline__ void ldsm_x4(uint32_t a, uint32_t& r0, uint32_t& r1,
                                        uint32_t& r2, uint32_t& r3) {
    asm volatile("ldmatrix.sync.aligned.m8n8.x4.shared.b16 {%0,%1,%2,%3}, [%4];"
                 : "=r"(r0), "=r"(r1), "=r"(r2), "=r"(r3) : "r"(a));
}
__device__ __forceinline__ void ldsm_x4t(uint32_t a, uint32_t& r0, uint32_t& r1,
                                         uint32_t& r2, uint32_t& r3) {
    asm volatile("ldmatrix.sync.aligned.m8n8.x4.trans.shared.b16 {%0,%1,%2,%3}, [%4];"
                 : "=r"(r0), "=r"(r1), "=r"(r2), "=r"(r3) : "r"(a));
}
__device__ __forceinline__ void ldsm_x2(uint32_t a, uint32_t& r0, uint32_t& r1) {
    asm volatile("ldmatrix.sync.aligned.m8n8.x2.shared.b16 {%0,%1}, [%2];"
                 : "=r"(r0), "=r"(r1) : "r"(a));
}
__device__ __forceinline__ void mma16816(float* d, uint32_t a0, uint32_t a1,
                                         uint32_t a2, uint32_t a3,
                                         uint32_t b0, uint32_t b1) {
    asm volatile("mma.sync.aligned.m16n8k16.row.col.f32.f16.f16.f32 "
                 "{%0,%1,%2,%3}, {%4,%5,%6,%7}, {%8,%9}, {%0,%1,%2,%3};"
                 : "+f"(d[0]), "+f"(d[1]), "+f"(d[2]), "+f"(d[3])
                 : "r"(a0), "r"(a1), "r"(a2), "r"(a3), "r"(b0), "r"(b1));
}
__device__ __forceinline__ void mma16816h(uint32_t& d0, uint32_t& d1,
                                          uint32_t a0, uint32_t a1,
                                          uint32_t a2, uint32_t a3,
                                          uint32_t b0, uint32_t b1) {
    asm volatile("mma.sync.aligned.m16n8k16.row.col.f16.f16.f16.f16 "
                 "{%0,%1}, {%2,%3,%4,%5}, {%6,%7}, {%0,%1};"
                 : "+r"(d0), "+r"(d1)
                 : "r"(a0), "r"(a1), "r"(a2), "r"(a3), "r"(b0), "r"(b1));
}
__device__ __forceinline__ uint32_t ex2h2(uint32_t a) {
    uint32_t r;
    asm("ex2.approx.f16x2 %0, %1;" : "=r"(r) : "r"(a));
    return r;
}
__device__ __forceinline__ uint32_t h2u(__half2 h) { return *(uint32_t*)&h; }
__device__ __forceinline__ __half2 u2h(uint32_t u) { return *(__half2*)&u; }

// ---------------- smem layout (bytes) ----------------
constexpr int SM_Q    = 0;                        // Q staging (dead after prologue)
constexpr int SM_KV   = 64 * LDQ;                 // 17408
constexpr int KBUF    = 72 * LDKB;                // 10368
constexpr int NBUF    = 5;
constexpr int SM_O    = SM_KV + NBUF * KBUF;      // 69248: O accum [128][LDO] f32
constexpr int SM_L    = SM_O + BM * LDO * 4;      // 104064: l per row [128] f32
constexpr int SMEM_BYTES = SM_L + BM * 4;         // 104576 -> 2 CTAs/SM

constexpr float L2E    = 1.4426950408889634f;
constexpr float MARGIN = 20.0f;

// non-skipped tile: O loaded from smem, rescale+GEMM2, stored back
__device__ __forceinline__ void process_tile(
    const uint32_t* Sc0, const uint32_t* Sc1, uint32_t kvb,
    float& M0, float& M1, float* O0 /* thread's O base: row r0 + 2q */,
    float* Ol, int l16, int hsel, float mx0, float mx1)
{
    mx0 = fmaxf(mx0, __shfl_xor_sync(0xffffffffu, mx0, 1));
    mx0 = fmaxf(mx0, __shfl_xor_sync(0xffffffffu, mx0, 2));
    mx1 = fmaxf(mx1, __shfl_xor_sync(0xffffffffu, mx1, 1));
    mx1 = fmaxf(mx1, __shfl_xor_sync(0xffffffffu, mx1, 2));

    // load O from smem
    float O[8][4];
    #pragma unroll
    for (int ct = 0; ct < 8; ++ct) {
        float2 lo = *(const float2*)(O0 + 8 * ct);
        float2 hi = *(const float2*)(O0 + 8 * LDO + 8 * ct);
        O[ct][0] = lo.x; O[ct][1] = lo.y; O[ct][2] = hi.x; O[ct][3] = hi.y;
    }

    const bool chg = (mx0 > M0) | (mx1 > M1);
    if (__any_sync(0xffffffffu, chg)) {
        const float nM0 = fmaxf(M0, mx0), nM1 = fmaxf(M1, mx1);
        const float sc0 = exp2f((M0 - nM0) * L2E);
        const float sc1 = exp2f((M1 - nM1) * L2E);
        M0 = nM0; M1 = nM1;
        #pragma unroll
        for (int ct = 0; ct < 8; ++ct) {
            O[ct][0] *= sc0; O[ct][1] *= sc0;
            O[ct][2] *= sc1; O[ct][3] *= sc1;
        }
        Ol[0] *= sc0; Ol[1] *= sc0; Ol[2] *= sc1; Ol[3] *= sc1;
    }

    const __half2 m0h = __float2half2_rn(M0);
    const __half2 m1h = __float2half2_rn(M1);
    const __half2 l2e = __float2half2_rn(L2E);
    uint32_t P01[8], P23[8];
    #pragma unroll
    for (int nt = 0; nt < 8; ++nt) {
        P01[nt] = ex2h2(h2u(__hmul2(__hsub2(u2h(Sc0[nt]), m0h), l2e)));
        P23[nt] = ex2h2(h2u(__hmul2(__hsub2(u2h(Sc1[nt]), m1h), l2e)));
    }

    #pragma unroll
    for (int kk = 0; kk < 4; ++kk) {
        const uint32_t a0 = P01[2 * kk],     a1 = P23[2 * kk];
        const uint32_t a2 = P01[2 * kk + 1], a3 = P23[2 * kk + 1];
        #pragma unroll
        for (int ct2 = 0; ct2 < 4; ++ct2) {
            uint32_t r0, r1, r2, r3;
            ldsm_x4(kvb + (ct2 * 16 + l16) * LDKB + kk * 32 + hsel, r0, r1, r2, r3);
            mma16816(O[2 * ct2],     a0, a1, a2, a3, r0, r2);
            mma16816(O[2 * ct2 + 1], a0, a1, a2, a3, r1, r3);
        }
        {
            uint32_t o0, o1;
            ldsm_x2(kvb + (64 + (l16 & 7)) * LDKB + kk * 32 + ((l16 >> 3) * 16), o0, o1);
            mma16816(Ol, a0, a1, a2, a3, o0, o1);
        }
    }

    // store O back
    #pragma unroll
    for (int ct = 0; ct < 8; ++ct) {
        *(float2*)(O0 + 8 * ct)           = make_float2(O[ct][0], O[ct][1]);
        *(float2*)(O0 + 8 * LDO + 8 * ct) = make_float2(O[ct][2], O[ct][3]);
    }
}

__global__ __launch_bounds__(256, 2)
void attn_mma_kernel(const float* __restrict__ x, float* __restrict__ out)
{
    extern __shared__ char smraw[];
    const uint32_t sb = smem_u32(smraw);

    const int tid  = threadIdx.x;
    const int w    = tid >> 5;
    const int lane = tid & 31;
    const int g    = lane >> 2;
    const int q    = lane & 3;
    const int l16  = lane & 15;
    const int hsel = (lane >> 4) * 16;

    const int b  = blockIdx.y;
    const int m0 = blockIdx.x * BM;
    const int jsel0 = blockIdx.x * 2;
    const size_t bC = (size_t)b * C;

    float* Osm = (float*)(smraw + SM_O);
    float* Lsm = (float*)(smraw + SM_L);
    const int r0row = w * 16 + g;
    float* O0 = Osm + r0row * LDO + 2 * q;

    // ones rows of K buffers + zero O accumulator
    for (int idx = tid; idx < NBUF * 8 * 9; idx += 256) {
        int buf = idx / 72, rem = idx % 72;
        int r = rem / 9, ch = rem % 9;
        uint32_t a = sb + SM_KV + buf * KBUF + (64 + r) * LDKB + ch * 16;
        const uint32_t one2 = 0x3C003C00u;
        asm volatile("st.shared.v4.b32 [%0], {%1,%1,%1,%1};" :: "r"(a), "r"(one2));
    }
    for (int idx = tid; idx < BM * LDO; idx += 256) Osm[idx] = 0.f;

    // prologue: group0 = Q + K0, group1 = K1, group2 = K2
    #pragma unroll
    for (int it = 0; it < 4; ++it) {
        int idx = tid + it * 256;
        int r = idx >> 4, ch = idx & 15;
        cpa16(sb + SM_Q + r * LDQ + ch * 16, g_cn + (bC + r) * NPOS + m0 + ch * 8);
    }
    {
        const int n0 = (jsel0 & (NT - 1)) * BN;
        #pragma unroll
        for (int it = 0; it < 2; ++it) {
            int idx = tid + it * 256;
            int r = idx >> 3, ch = idx & 7;
            cpa16(sb + SM_KV + r * LDKB + ch * 16, g_cn + (bC + r) * NPOS + n0 + ch * 8);
        }
    }
    CP_COMMIT();
    #pragma unroll
    for (int pt = 1; pt < 3; ++pt) {
        uint32_t base = sb + SM_KV + pt * KBUF;
        const int n0 = ((jsel0 + pt) & (NT - 1)) * BN;
        #pragma unroll
        for (int it = 0; it < 2; ++it) {
            int idx = tid + it * 256;
            int r = idx >> 3, ch = idx & 7;
            cpa16(base + r * LDKB + ch * 16, g_cn + (bC + r) * NPOS + n0 + ch * 8);
        }
        CP_COMMIT();
    }

    CP_WAIT1();
    __syncthreads();
    uint32_t QF[4][4];
    #pragma unroll
    for (int k = 0; k < 4; ++k) {
        uint32_t r0, r1, r2, r3;
        ldsm_x4t(sb + SM_Q + (k * 16 + l16) * LDQ + w * 32 + hsel, r0, r1, r2, r3);
        QF[k][0] = r0; QF[k][1] = r2; QF[k][2] = r1; QF[k][3] = r3;
    }

    // seed running max from precomputed self logits
    float M0 = g_diag[b * NPOS + m0 + r0row];
    float M1 = g_diag[b * NPOS + m0 + r0row + 8];
    float Ol[4] = {0.f, 0.f, 0.f, 0.f};

    int bt = 0, pf = 3;

    for (int t = 0; t < NT; t += 2) {
        CP_WAIT1();
        __syncthreads();

        #pragma unroll
        for (int pt = 3; pt <= 4; ++pt) {
            if (t + pt < NT) {
                const int n0 = ((jsel0 + t + pt) & (NT - 1)) * BN;
                uint32_t base = sb + SM_KV + pf * KBUF;
                #pragma unroll
                for (int it = 0; it < 2; ++it) {
                    int idx = tid + it * 256;
                    int r = idx >> 3, ch = idx & 7;
                    cpa16(base + r * LDKB + ch * 16,
                          g_cn + (bC + r) * NPOS + n0 + ch * 8);
                }
            }
            CP_COMMIT();
            if (++pf == NBUF) pf = 0;
        }

        #pragma unroll
        for (int u = 0; u < 2; ++u) {
            const uint32_t kvb = sb + SM_KV + bt * KBUF;
            if (++bt == NBUF) bt = 0;

            // GEMM1 screen (f16-acc, 2-slice pipelined)
            uint32_t Sc0[8], Sc1[8];
            #pragma unroll
            for (int i = 0; i < 8; ++i) { Sc0[i] = 0u; Sc1[i] = 0u; }

            const uint32_t kr = kvb + l16 * LDKB + hsel;
            uint32_t Bb[2][16];
            #pragma unroll
            for (int nt2 = 0; nt2 < 4; ++nt2)
                ldsm_x4t(kr + nt2 * 32, Bb[0][4 * nt2], Bb[0][4 * nt2 + 1],
                         Bb[0][4 * nt2 + 2], Bb[0][4 * nt2 + 3]);

            #pragma unroll
            for (int k = 0; k < 4; ++k) {
                const int cur = k & 1;
                if (k < 3) {
                    const uint32_t krn = kr + (k + 1) * 16 * LDKB;
                    #pragma unroll
                    for (int nt2 = 0; nt2 < 4; ++nt2)
                        ldsm_x4t(krn + nt2 * 32,
                                 Bb[cur ^ 1][4 * nt2],     Bb[cur ^ 1][4 * nt2 + 1],
                                 Bb[cur ^ 1][4 * nt2 + 2], Bb[cur ^ 1][4 * nt2 + 3]);
                }
                #pragma unroll
                for (int nt2 = 0; nt2 < 4; ++nt2) {
                    mma16816h(Sc0[2 * nt2],     Sc1[2 * nt2],
                              QF[k][0], QF[k][1], QF[k][2], QF[k][3],
                              Bb[cur][4 * nt2], Bb[cur][4 * nt2 + 1]);
                    mma16816h(Sc0[2 * nt2 + 1], Sc1[2 * nt2 + 1],
                              QF[k][0], QF[k][1], QF[k][2], QF[k][3],
                              Bb[cur][4 * nt2 + 2], Bb[cur][4 * nt2 + 3]);
                }
            }

            // per-lane max; one ballot decides skip
            __half2 lo = u2h(Sc0[0]), hi = u2h(Sc1[0]);
            #pragma unroll
            for (int i = 1; i < 8; ++i) {
                lo = __hmax2(lo, u2h(Sc0[i]));
                hi = __hmax2(hi, u2h(Sc1[i]));
            }
            float mx0 = fmaxf(__low2float(lo), __high2float(lo));
            float mx1 = fmaxf(__low2float(hi), __high2float(hi));

            const unsigned vote = __ballot_sync(0xffffffffu,
                (mx0 >= M0 - MARGIN) | (mx1 >= M1 - MARGIN));
            if (vote != 0)
                process_tile(Sc0, Sc1, kvb, M0, M1, O0, Ol, l16, hsel, mx0, mx1);
        }
    }

    // ---- epilogue: l to smem, invert, write out ----
    if (q == 0) {
        Lsm[r0row]     = Ol[0];
        Lsm[r0row + 8] = Ol[2];
    }
    __syncthreads();
    if (tid < BM) Lsm[tid] = 1.0f / Lsm[tid];
    __syncthreads();

    #pragma unroll
    for (int it = 0; it < 32; ++it) {
        int flat = it * 256 + tid;
        int m = flat & 127, c = flat >> 7;
        const size_t o = (bC + c) * NPOS + m0 + m;
        out[o] = x[o] + Osm[m * LDO + c] * Lsm[m];
    }
}

extern "C" void kernel_launch(void* const* d_in, const int* in_sizes, int n_in,
                              void* d_out, int out_size)
{
    const float* x = (const float*)d_in[0];
    float* out = (float*)d_out;

    prep_kernel<<<(NB * C * NPOS) / 1024, 256>>>(x);
    diag_kernel<<<dim3(NPOS / 256, NB), 256>>>();

    cudaFuncSetAttribute(attn_mma_kernel,
                         cudaFuncAttributeMaxDynamicSharedMemorySize, SMEM_BYTES);
    dim3 grid(NPOS / BM, NB);
    attn_mma_kernel<<<grid, 256, SMEM_BYTES>>>(x, out);
}

// round 15
// speedup vs baseline: 1.1195x; 1.1195x over previous
#include <cuda_runtime.h>
#include <cuda_fp16.h>
#include <cstdint>

// ChannelAttentionModule: out = x + (F @ softmax(F^T F)^T), F = x.reshape(B,C,N)
// B=8, C=64, N=4096. fp16 mma.sync FA2, one-hot-aware tile skip.
// R15 = R12 + deep cp.async pipeline: NBUF=8, ONE commit group per tile-pair,
// prefetch distance 3 pairs (6 tiles) -> waits are satisfied on arrival.

constexpr int C    = 64;
constexpr int NPOS = 4096;
constexpr int NB   = 8;
constexpr int BM   = 128;
constexpr int BN   = 64;
constexpr int NT   = NPOS / BN;    // 64 tiles
constexpr int LDKB = 144;
constexpr int LDQ  = 272;
constexpr int LDO  = 68;

__device__ __half g_cn[(size_t)NB * C * NPOS];   // fp16 x, [b][c][n]

__global__ void prep_kernel(const float* __restrict__ x) {
    size_t i = ((size_t)blockIdx.x * 256 + threadIdx.x) * 4;
    float4 v = *(const float4*)(x + i);
    *(__half2*)(g_cn + i)     = __floats2half2_rn(v.x, v.y);
    *(__half2*)(g_cn + i + 2) = __floats2half2_rn(v.z, v.w);
}

// ---------------- PTX helpers ----------------
__device__ __forceinline__ uint32_t smem_u32(const void* p) {
    uint32_t a;
    asm("{ .reg .u64 t; cvta.to.shared.u64 t, %1; cvt.u32.u64 %0, t; }" : "=r"(a) : "l"(p));
    return a;
}
__device__ __forceinline__ void cpa16(uint32_t dst, const void* src) {
    asm volatile("cp.async.ca.shared.global [%0], [%1], 16;"
                 :: "r"(dst), "l"(__cvta_generic_to_global(src)));
}
#define CP_COMMIT() asm volatile("cp.async.commit_group;" ::: "memory")
#define CP_WAIT2()  asm volatile("cp.async.wait_group 2;" ::: "memory")

__device__ __forceinline__ void ldsm_x4(uint32_t a, uint32_t& r0, uint32_t& r1,
                                        uint32_t& r2, uint32_t& r3) {
    asm volatile("ldmatrix.sync.aligned.m8n8.x4.shared.b16 {%0,%1,%2,%3}, [%4];"
                 : "=r"(r0), "=r"(r1), "=r"(r2), "=r"(r3) : "r"(a));
}
__device__ __forceinline__ void ldsm_x4t(uint32_t a, uint32_t& r0, uint32_t& r1,
                                         uint32_t& r2, uint32_t& r3) {
    asm volatile("ldmatrix.sync.aligned.m8n8.x4.trans.shared.b16 {%0,%1,%2,%3}, [%4];"
                 : "=r"(r0), "=r"(r1), "=r"(r2), "=r"(r3) : "r"(a));
}
__device__ __forceinline__ void ldsm_x2(uint32_t a, uint32_t& r0, uint32_t& r1) {
    asm volatile("ldmatrix.sync.aligned.m8n8.x2.shared.b16 {%0,%1}, [%2];"
                 : "=r"(r0), "=r"(r1) : "r"(a));
}
__device__ __forceinline__ void mma16816(float* d, uint32_t a0, uint32_t a1,
                                         uint32_t a2, uint32_t a3,
                                         uint32_t b0, uint32_t b1) {
    asm volatile("mma.sync.aligned.m16n8k16.row.col.f32.f16.f16.f32 "
                 "{%0,%1,%2,%3}, {%4,%5,%6,%7}, {%8,%9}, {%0,%1,%2,%3};"
                 : "+f"(d[0]), "+f"(d[1]), "+f"(d[2]), "+f"(d[3])
                 : "r"(a0), "r"(a1), "r"(a2), "r"(a3), "r"(b0), "r"(b1));
}
__device__ __forceinline__ void mma16816h(uint32_t& d0, uint32_t& d1,
                                          uint32_t a0, uint32_t a1,
                                          uint32_t a2, uint32_t a3,
                                          uint32_t b0, uint32_t b1) {
    asm volatile("mma.sync.aligned.m16n8k16.row.col.f16.f16.f16.f16 "
                 "{%0,%1}, {%2,%3,%4,%5}, {%6,%7}, {%0,%1};"
                 : "+r"(d0), "+r"(d1)
                 : "r"(a0), "r"(a1), "r"(a2), "r"(a3), "r"(b0), "r"(b1));
}
__device__ __forceinline__ uint32_t ex2h2(uint32_t a) {
    uint32_t r;
    asm("ex2.approx.f16x2 %0, %1;" : "=r"(r) : "r"(a));
    return r;
}
__device__ __forceinline__ uint32_t h2u(__half2 h) { return *(uint32_t*)&h; }
__device__ __forceinline__ __half2 u2h(uint32_t u) { return *(__half2*)&u; }

// ---------------- smem layout (bytes) ----------------
constexpr int SM_Q    = 0;                        // Q staging [64][LDQ] = 17408
constexpr int SM_KV   = 64 * LDQ;
constexpr int KBUF    = 72 * LDKB;                // 10368 (64 data + 8 ones rows)
constexpr int NBUF    = 8;
constexpr int SMEM_BYTES = SM_KV + NBUF * KBUF;   // 100352 -> 2 CTAs/SM

constexpr float L2E    = 1.4426950408889634f;
constexpr float MARGIN = 20.0f;

__global__ __launch_bounds__(256, 2)
void attn_mma_kernel(const float* __restrict__ x, float* __restrict__ out)
{
    extern __shared__ char smraw[];
    const uint32_t sb = smem_u32(smraw);

    const int tid  = threadIdx.x;
    const int w    = tid >> 5;
    const int lane = tid & 31;
    const int g    = lane >> 2;
    const int q    = lane & 3;
    const int l16  = lane & 15;
    const int hsel = (lane >> 4) * 16;

    const int b  = blockIdx.y;
    const int m0 = blockIdx.x * BM;
    const int jsel0 = blockIdx.x * 2;          // self tiles first
    const size_t bC = (size_t)b * C;

    // ones rows (c=64..71) of every K buffer
    for (int idx = tid; idx < NBUF * 8 * 9; idx += 256) {
        int buf = idx / 72, rem = idx % 72;
        int r = rem / 9, ch = rem % 9;
        uint32_t a = sb + SM_KV + buf * KBUF + (64 + r) * LDKB + ch * 16;
        const uint32_t one2 = 0x3C003C00u;
        asm volatile("st.shared.v4.b32 [%0], {%1,%1,%1,%1};" :: "r"(a), "r"(one2));
    }

    // ---- prologue: group0 = Q + tiles 0,1; group1 = tiles 2,3; group2 = 4,5 ----
    #pragma unroll
    for (int it = 0; it < 4; ++it) {
        int idx = tid + it * 256;
        int r = idx >> 4, ch = idx & 15;
        cpa16(sb + SM_Q + r * LDQ + ch * 16, g_cn + (bC + r) * NPOS + m0 + ch * 8);
    }
    #pragma unroll
    for (int pr = 0; pr < 3; ++pr) {
        #pragma unroll
        for (int u = 0; u < 2; ++u) {
            const int tt = 2 * pr + u;
            const int n0 = ((jsel0 + tt) & (NT - 1)) * BN;
            uint32_t base = sb + SM_KV + tt * KBUF;
            #pragma unroll
            for (int it = 0; it < 2; ++it) {
                int idx = tid + it * 256;
                int r = idx >> 3, ch = idx & 7;
                cpa16(base + r * LDKB + ch * 16, g_cn + (bC + r) * NPOS + n0 + ch * 8);
            }
        }
        CP_COMMIT();   // one group per pair
    }

    // ---- wait group0 (Q + pair0), hoist Q fragments ----
    CP_WAIT2();
    __syncthreads();
    uint32_t QF[4][4];
    #pragma unroll
    for (int k = 0; k < 4; ++k) {
        uint32_t r0, r1, r2, r3;
        ldsm_x4t(sb + SM_Q + (k * 16 + l16) * LDQ + w * 32 + hsel, r0, r1, r2, r3);
        QF[k][0] = r0; QF[k][1] = r2; QF[k][2] = r1; QF[k][3] = r3;
    }

    float M0 = -1e30f, M1 = -1e30f;
    float O[8][4], Ol[4];
    #pragma unroll
    for (int i = 0; i < 8; ++i)
        #pragma unroll
        for (int k = 0; k < 4; ++k) O[i][k] = 0.f;
    #pragma unroll
    for (int k = 0; k < 4; ++k) Ol[k] = 0.f;

    for (int t = 0; t < NT; t += 2) {
        CP_WAIT2();           // pair t/2's group retired (3 pairs of slack)
        __syncthreads();      // all warps past pair t/2-1 (frees bufs (t+6)%8,(t+7)%8)

        // prefetch pair t/2+3 (tiles t+6, t+7), single group
        #pragma unroll
        for (int u = 6; u <= 7; ++u) {
            if (t + u < NT) {
                const int n0 = ((jsel0 + t + u) & (NT - 1)) * BN;
                uint32_t base = sb + SM_KV + ((t + u) & (NBUF - 1)) * KBUF;
                #pragma unroll
                for (int it = 0; it < 2; ++it) {
                    int idx = tid + it * 256;
                    int r = idx >> 3, ch = idx & 7;
                    cpa16(base + r * LDKB + ch * 16,
                          g_cn + (bC + r) * NPOS + n0 + ch * 8);
                }
            }
        }
        CP_COMMIT();          // unconditional: dense group numbering

        #pragma unroll
        for (int u = 0; u < 2; ++u) {
            const uint32_t kvb = sb + SM_KV + ((t + u) & (NBUF - 1)) * KBUF;

            // ---- GEMM1 screen (f16-acc, 2-slice pipelined) ----
            uint32_t Sc0[8], Sc1[8];
            #pragma unroll
            for (int i = 0; i < 8; ++i) { Sc0[i] = 0u; Sc1[i] = 0u; }

            const uint32_t kr = kvb + l16 * LDKB + hsel;
            uint32_t Bb[2][16];
            #pragma unroll
            for (int nt2 = 0; nt2 < 4; ++nt2)
                ldsm_x4t(kr + nt2 * 32, Bb[0][4 * nt2], Bb[0][4 * nt2 + 1],
                         Bb[0][4 * nt2 + 2], Bb[0][4 * nt2 + 3]);

            #pragma unroll
            for (int k = 0; k < 4; ++k) {
                const int cur = k & 1;
                if (k < 3) {
                    const uint32_t krn = kr + (k + 1) * 16 * LDKB;
                    #pragma unroll
                    for (int nt2 = 0; nt2 < 4; ++nt2)
                        ldsm_x4t(krn + nt2 * 32,
                                 Bb[cur ^ 1][4 * nt2],     Bb[cur ^ 1][4 * nt2 + 1],
                                 Bb[cur ^ 1][4 * nt2 + 2], Bb[cur ^ 1][4 * nt2 + 3]);
                }
                #pragma unroll
                for (int nt2 = 0; nt2 < 4; ++nt2) {
                    mma16816h(Sc0[2 * nt2],     Sc1[2 * nt2],
                              QF[k][0], QF[k][1], QF[k][2], QF[k][3],
                              Bb[cur][4 * nt2], Bb[cur][4 * nt2 + 1]);
                    mma16816h(Sc0[2 * nt2 + 1], Sc1[2 * nt2 + 1],
                              QF[k][0], QF[k][1], QF[k][2], QF[k][3],
                              Bb[cur][4 * nt2 + 2], Bb[cur][4 * nt2 + 3]);
                }
            }

            // ---- per-lane max, one-ballot skip ----
            __half2 lo = u2h(Sc0[0]), hi = u2h(Sc1[0]);
            #pragma unroll
            for (int i = 1; i < 8; ++i) {
                lo = __hmax2(lo, u2h(Sc0[i]));
                hi = __hmax2(hi, u2h(Sc1[i]));
            }
            float mx0 = fmaxf(__low2float(lo), __high2float(lo));
            float mx1 = fmaxf(__low2float(hi), __high2float(hi));

            const unsigned vote = __ballot_sync(0xffffffffu,
                (mx0 >= M0 - MARGIN) | (mx1 >= M1 - MARGIN));
            if (vote != 0) {
                mx0 = fmaxf(mx0, __shfl_xor_sync(0xffffffffu, mx0, 1));
                mx0 = fmaxf(mx0, __shfl_xor_sync(0xffffffffu, mx0, 2));
                mx1 = fmaxf(mx1, __shfl_xor_sync(0xffffffffu, mx1, 1));
                mx1 = fmaxf(mx1, __shfl_xor_sync(0xffffffffu, mx1, 2));
                const bool chg = (mx0 > M0) | (mx1 > M1);
                if (__any_sync(0xffffffffu, chg)) {
                    const float nM0 = fmaxf(M0, mx0), nM1 = fmaxf(M1, mx1);
                    const float sc0 = exp2f((M0 - nM0) * L2E);
                    const float sc1 = exp2f((M1 - nM1) * L2E);
                    M0 = nM0; M1 = nM1;
                    #pragma unroll
                    for (int ct = 0; ct < 8; ++ct) {
                        O[ct][0] *= sc0; O[ct][1] *= sc0;
                        O[ct][2] *= sc1; O[ct][3] *= sc1;
                    }
                    Ol[0] *= sc0; Ol[1] *= sc0; Ol[2] *= sc1; Ol[3] *= sc1;
                }

                const __half2 m0h = __float2half2_rn(M0);
                const __half2 m1h = __float2half2_rn(M1);
                const __half2 l2e = __float2half2_rn(L2E);
                uint32_t P01[8], P23[8];
                #pragma unroll
                for (int nt = 0; nt < 8; ++nt) {
                    P01[nt] = ex2h2(h2u(__hmul2(__hsub2(u2h(Sc0[nt]), m0h), l2e)));
                    P23[nt] = ex2h2(h2u(__hmul2(__hsub2(u2h(Sc1[nt]), m1h), l2e)));
                }

                // GEMM2: [O | l] += P @ [V | 1]; V = non-trans ldmatrix of K tile
                #pragma unroll
                for (int kk = 0; kk < 4; ++kk) {
                    const uint32_t a0 = P01[2 * kk],     a1 = P23[2 * kk];
                    const uint32_t a2 = P01[2 * kk + 1], a3 = P23[2 * kk + 1];
                    #pragma unroll
                    for (int ct2 = 0; ct2 < 4; ++ct2) {
                        uint32_t r0, r1, r2, r3;
                        ldsm_x4(kvb + (ct2 * 16 + l16) * LDKB + kk * 32 + hsel,
                                r0, r1, r2, r3);
                        mma16816(O[2 * ct2],     a0, a1, a2, a3, r0, r2);
                        mma16816(O[2 * ct2 + 1], a0, a1, a2, a3, r1, r3);
                    }
                    {
                        uint32_t o0, o1;
                        ldsm_x2(kvb + (64 + (l16 & 7)) * LDKB + kk * 32 +
                                ((l16 >> 3) * 16), o0, o1);
                        mma16816(Ol, a0, a1, a2, a3, o0, o1);
                    }
                }
            }
        }
    }

    __syncthreads();

    // ---- epilogue ----
    float* Sst = (float*)smraw;
    const float i0 = 1.0f / Ol[0], i1 = 1.0f / Ol[2];
    const int r0 = w * 16 + g, r1 = r0 + 8;
    #pragma unroll
    for (int ct = 0; ct < 8; ++ct) {
        Sst[r0 * LDO + 8 * ct + 2 * q]     = O[ct][0] * i0;
        Sst[r0 * LDO + 8 * ct + 2 * q + 1] = O[ct][1] * i0;
        Sst[r1 * LDO + 8 * ct + 2 * q]     = O[ct][2] * i1;
        Sst[r1 * LDO + 8 * ct + 2 * q + 1] = O[ct][3] * i1;
    }
    __syncthreads();

    #pragma unroll
    for (int it = 0; it < 32; ++it) {
        int flat = it * 256 + tid;
        int m = flat & 127, c = flat >> 7;
        const size_t o = (bC + c) * NPOS + m0 + m;
        out[o] = x[o] + Sst[m * LDO + c];
    }
}

extern "C" void kernel_launch(void* const* d_in, const int* in_sizes, int n_in,
                              void* d_out, int out_size)
{
    const float* x = (const float*)d_in[0];
    float* out = (float*)d_out;

    prep_kernel<<<(NB * C * NPOS) / 1024, 256>>>(x);

    cudaFuncSetAttribute(attn_mma_kernel,
                         cudaFuncAttributeMaxDynamicSharedMemorySize, SMEM_BYTES);
    dim3 grid(NPOS / BM, NB);
    attn_mma_kernel<<<grid, 256, SMEM_BYTES>>>(x, out);
}